// round 1
// baseline (speedup 1.0000x reference)
#include <cuda_runtime.h>

// Problem constants
#define B_   1024
#define T_   512
#define F_   32
#define E_   16
#define H_   128
#define G_   384      // 3*H
#define KX_  48       // F + E
#define ROWS 8        // batch rows per block
#define NBLK (B_/ROWS)  // 128 blocks
#define NTHR 384      // one thread per gate output

// Transposed / quad-packed weights: layout [k/4][g][4] so each thread does
// one coalesced LDG.128 per 4-k chunk.
__device__ float Wq_ih0[KX_*G_];
__device__ float Wq_hh0[H_*G_];
__device__ float Wq_ih1[H_*G_];
__device__ float Wq_hh1[H_*G_];

__global__ void prep_kernel(const float* __restrict__ W_ih0,
                            const float* __restrict__ W_hh0,
                            const float* __restrict__ W_ih1,
                            const float* __restrict__ W_hh1) {
    int idx = blockIdx.x * blockDim.x + threadIdx.x;
    if (idx < KX_ * G_) {
        int g = idx / KX_, k = idx % KX_;
        Wq_ih0[((k >> 2) * G_ + g) * 4 + (k & 3)] = W_ih0[idx];
    }
    if (idx < H_ * G_) {
        int g = idx / H_, k = idx % H_;
        int dst = ((k >> 2) * G_ + g) * 4 + (k & 3);
        Wq_hh0[dst] = W_hh0[idx];
        Wq_ih1[dst] = W_ih1[idx];
        Wq_hh1[dst] = W_hh1[idx];
    }
}

__device__ __forceinline__ float sigmoidf_(float v) {
    v = fminf(fmaxf(v, -30.f), 30.f);
    return 1.f / (1.f + __expf(-v));
}
__device__ __forceinline__ float tanhf_(float v) {
    v = fminf(fmaxf(v, -15.f), 15.f);
    float e = __expf(2.f * v);
    return (e - 1.f) / (e + 1.f);
}

__global__ void __launch_bounds__(NTHR, 1) gru_kernel(
    const float* __restrict__ x,         // (B, T, F)
    const int*   __restrict__ ticker,    // (B,)
    const float* __restrict__ embed,     // (N_TICKERS, E)
    const float* __restrict__ b_ih0, const float* __restrict__ b_hh0,
    const float* __restrict__ b_ih1, const float* __restrict__ b_hh1,
    const float* __restrict__ head_w1, const float* __restrict__ head_b1,
    const float* __restrict__ head_w2, const float* __restrict__ head_b2,
    float* __restrict__ y)               // (B,)
{
    __shared__ __align__(16) float xe[ROWS][KX_];    // [x | emb] for current t
    __shared__ __align__(16) float h0[ROWS][H_];
    __shared__ __align__(16) float h1[ROWS][H_];
    __shared__ __align__(16) float rz[ROWS][2 * H_]; // r and z gates

    const int g  = threadIdx.x;          // gate index 0..383
    const int b0 = blockIdx.x * ROWS;

    // init states + constant embedding slice
    for (int i = g; i < ROWS * H_; i += NTHR) {
        (&h0[0][0])[i] = 0.f;
        (&h1[0][0])[i] = 0.f;
    }
    if (g < ROWS * E_) {
        int r = g / E_, e = g % E_;
        xe[r][F_ + e] = embed[(size_t)ticker[b0 + r] * E_ + e];
    }

    const float bi0 = b_ih0[g], bh0 = b_hh0[g];
    const float bi1 = b_ih1[g], bh1 = b_hh1[g];
    const bool  is_n = (g >= 2 * H_);
    const int   j    = g - 2 * H_;
    __syncthreads();

    for (int t = 0; t < T_; ++t) {
        // stage x[:, t, :] for this block's rows (coalesced: 32 floats/row)
        if (g < ROWS * F_) {
            int r = g >> 5, i = g & 31;
            xe[r][i] = x[((size_t)(b0 + r) * T_ + t) * F_ + i];
        }
        __syncthreads();

        // ===================== layer 0 =====================
        float ax[ROWS], ah[ROWS];
#pragma unroll
        for (int r = 0; r < ROWS; r++) { ax[r] = 0.f; ah[r] = 0.f; }

        // gx: xcat (48) @ W_ih0^T
#pragma unroll
        for (int kk = 0; kk < KX_ / 4; kk++) {
            const float4 w = *(const float4*)(Wq_ih0 + ((size_t)kk * G_ + g) * 4);
#pragma unroll
            for (int r = 0; r < ROWS; r++) {
                const float4 v = *(const float4*)&xe[r][kk * 4];
                ax[r] += w.x * v.x + w.y * v.y + w.z * v.z + w.w * v.w;
            }
        }
        // gh: h0 (128) @ W_hh0^T
#pragma unroll 8
        for (int kk = 0; kk < H_ / 4; kk++) {
            const float4 w = *(const float4*)(Wq_hh0 + ((size_t)kk * G_ + g) * 4);
#pragma unroll
            for (int r = 0; r < ROWS; r++) {
                const float4 v = *(const float4*)&h0[r][kk * 4];
                ah[r] += w.x * v.x + w.y * v.y + w.z * v.z + w.w * v.w;
            }
        }
        if (!is_n) {
#pragma unroll
            for (int r = 0; r < ROWS; r++)
                rz[r][g] = sigmoidf_(ax[r] + ah[r] + bi0 + bh0);
        }
        __syncthreads();
        if (is_n) {
#pragma unroll
            for (int r = 0; r < ROWS; r++) {
                float nn = tanhf_(ax[r] + bi0 + rz[r][j] * (ah[r] + bh0));
                float z  = rz[r][H_ + j];
                h0[r][j] = nn + z * (h0[r][j] - nn);   // (1-z)*n + z*h
            }
        }
        __syncthreads();

        // ===================== layer 1 =====================
#pragma unroll
        for (int r = 0; r < ROWS; r++) { ax[r] = 0.f; ah[r] = 0.f; }
#pragma unroll 8
        for (int kk = 0; kk < H_ / 4; kk++) {
            const float4 wi = *(const float4*)(Wq_ih1 + ((size_t)kk * G_ + g) * 4);
            const float4 wh = *(const float4*)(Wq_hh1 + ((size_t)kk * G_ + g) * 4);
#pragma unroll
            for (int r = 0; r < ROWS; r++) {
                const float4 u = *(const float4*)&h0[r][kk * 4];
                const float4 v = *(const float4*)&h1[r][kk * 4];
                ax[r] += wi.x * u.x + wi.y * u.y + wi.z * u.z + wi.w * u.w;
                ah[r] += wh.x * v.x + wh.y * v.y + wh.z * v.z + wh.w * v.w;
            }
        }
        if (!is_n) {
#pragma unroll
            for (int r = 0; r < ROWS; r++)
                rz[r][g] = sigmoidf_(ax[r] + ah[r] + bi1 + bh1);
        }
        __syncthreads();
        if (is_n) {
#pragma unroll
            for (int r = 0; r < ROWS; r++) {
                float nn = tanhf_(ax[r] + bi1 + rz[r][j] * (ah[r] + bh1));
                float z  = rz[r][H_ + j];
                h1[r][j] = nn + z * (h1[r][j] - nn);
            }
        }
        __syncthreads();
    }

    // ===================== head =====================
    // hid = relu(h1_last @ head_w1^T + b1);  y = hid @ head_w2^T + b2
    if (g < H_) {
        const float w2 = head_w2[g];
#pragma unroll
        for (int r = 0; r < ROWS; r++) {
            float acc = head_b1[g];
            for (int k = 0; k < H_; k += 4) {
                const float4 w = *(const float4*)&head_w1[g * H_ + k];
                const float4 v = *(const float4*)&h1[r][k];
                acc += w.x * v.x + w.y * v.y + w.z * v.z + w.w * v.w;
            }
            rz[r][g] = fmaxf(acc, 0.f) * w2;
        }
    }
    __syncthreads();
    if (g < ROWS) {
        float acc = head_b2[0];
        for (int k = 0; k < H_; k++) acc += rz[g][k];
        y[b0 + g] = acc;
    }
}

extern "C" void kernel_launch(void* const* d_in, const int* in_sizes, int n_in,
                              void* d_out, int out_size) {
    const float* x       = (const float*)d_in[0];
    const int*   ticker  = (const int*)  d_in[1];
    const float* embed   = (const float*)d_in[2];
    const float* W_ih0   = (const float*)d_in[3];
    const float* W_hh0   = (const float*)d_in[4];
    const float* b_ih0   = (const float*)d_in[5];
    const float* b_hh0   = (const float*)d_in[6];
    const float* W_ih1   = (const float*)d_in[7];
    const float* W_hh1   = (const float*)d_in[8];
    const float* b_ih1   = (const float*)d_in[9];
    const float* b_hh1   = (const float*)d_in[10];
    const float* head_w1 = (const float*)d_in[11];
    const float* head_b1 = (const float*)d_in[12];
    const float* head_w2 = (const float*)d_in[13];
    const float* head_b2 = (const float*)d_in[14];

    prep_kernel<<<(H_ * G_ + 255) / 256, 256>>>(W_ih0, W_hh0, W_ih1, W_hh1);
    gru_kernel<<<NBLK, NTHR>>>(x, ticker, embed,
                               b_ih0, b_hh0, b_ih1, b_hh1,
                               head_w1, head_b1, head_w2, head_b2,
                               (float*)d_out);
}

// round 2
// speedup vs baseline: 1.1046x; 1.1046x over previous
#include <cuda_runtime.h>

#define B_   1024
#define T_   512
#define F_   32
#define E_   16
#define H_   128
#define G_   384      // 3*H
#define KX_  48       // F + E
#define ROWS 8        // batch rows per block
#define NBLK (B_/ROWS)  // 128 blocks
#define NTHR 128      // thread j owns gates (j, H+j, 2H+j)

typedef unsigned long long u64;

// Quad-packed transposed weights: layout [k/4][g][4] -> thread loads one
// coalesced LDG.128 per 4-k chunk per gate.
__device__ __align__(16) float Wq_ih0[KX_*G_];
__device__ __align__(16) float Wq_hh0[H_*G_];
__device__ __align__(16) float Wq_ih1[H_*G_];
__device__ __align__(16) float Wq_hh1[H_*G_];

__global__ void prep_kernel(const float* __restrict__ W_ih0,
                            const float* __restrict__ W_hh0,
                            const float* __restrict__ W_ih1,
                            const float* __restrict__ W_hh1) {
    int idx = blockIdx.x * blockDim.x + threadIdx.x;
    if (idx < KX_ * G_) {
        int g = idx / KX_, k = idx % KX_;
        Wq_ih0[((k >> 2) * G_ + g) * 4 + (k & 3)] = W_ih0[idx];
    }
    if (idx < H_ * G_) {
        int g = idx / H_, k = idx % H_;
        int dst = ((k >> 2) * G_ + g) * 4 + (k & 3);
        Wq_hh0[dst] = W_hh0[idx];
        Wq_ih1[dst] = W_ih1[idx];
        Wq_hh1[dst] = W_hh1[idx];
    }
}

// packed 2-wide fp32 FMA (FFMA2) — ptxas never emits this from C++
__device__ __forceinline__ u64 fma2(u64 a, u64 b, u64 c) {
    u64 d;
    asm("fma.rn.f32x2 %0, %1, %2, %3;" : "=l"(d) : "l"(a), "l"(b), "l"(c));
    return d;
}
__device__ __forceinline__ float hsum2(u64 a) {
    float l, h;
    asm("mov.b64 {%0, %1}, %2;" : "=f"(l), "=f"(h) : "l"(a));
    return l + h;
}
// streaming 128-bit global load, L1-bypass (.cg) — keeps L1 for W_ih0
__device__ __forceinline__ ulonglong2 ldcg128(const float* p) {
    ulonglong2 v;
    asm("ld.global.cg.v2.u64 {%0, %1}, [%2];" : "=l"(v.x), "=l"(v.y) : "l"(p));
    return v;
}
__device__ __forceinline__ float sigmoidf_(float v) {
    return 1.f / (1.f + __expf(-v));
}
__device__ __forceinline__ float tanhf_(float v) {
    v = fminf(fmaxf(v, -15.f), 15.f);
    float e = __expf(2.f * v);
    return (e - 1.f) / (e + 1.f);
}

__global__ void __launch_bounds__(NTHR, 1) gru_kernel(
    const float* __restrict__ x,         // (B, T, F)
    const int*   __restrict__ ticker,    // (B,)
    const float* __restrict__ embed,     // (N_TICKERS, E)
    const float* __restrict__ b_ih0, const float* __restrict__ b_hh0,
    const float* __restrict__ b_ih1, const float* __restrict__ b_hh1,
    const float* __restrict__ head_w1, const float* __restrict__ head_b1,
    const float* __restrict__ head_w2, const float* __restrict__ head_b2,
    float* __restrict__ y)               // (B,)
{
    extern __shared__ float sm[];
    float* Wh1 = sm;                      // W_hh1 cached in SMEM: H_*G_ floats (192KB)
    float* h0s = sm + H_ * G_;            // ROWS*H_
    float* h1s = h0s + ROWS * H_;         // ROWS*H_
    float* xes = h1s + ROWS * H_;         // ROWS*KX_

    const int j  = threadIdx.x;           // hidden unit 0..127
    const int b0 = blockIdx.x * ROWS;

    // park W_hh1 in SMEM for the whole kernel
    {
        const float4* src = (const float4*)Wq_hh1;
        float4* dst = (float4*)Wh1;
        for (int i = j; i < H_ * G_ / 4; i += NTHR) dst[i] = src[i];
    }
    for (int i = j; i < ROWS * H_; i += NTHR) { h0s[i] = 0.f; h1s[i] = 0.f; }
    if (j < ROWS * E_) {
        int r = j / E_, e = j % E_;
        xes[r * KX_ + F_ + e] = embed[(size_t)ticker[b0 + r] * E_ + e];
    }

    const int gr = j, gz = H_ + j, gn = 2 * H_ + j;
    const float br0  = b_ih0[gr] + b_hh0[gr];
    const float bz0  = b_ih0[gz] + b_hh0[gz];
    const float bxn0 = b_ih0[gn], bhn0 = b_hh0[gn];
    const float br1  = b_ih1[gr] + b_hh1[gr];
    const float bz1  = b_ih1[gz] + b_hh1[gz];
    const float bxn1 = b_ih1[gn], bhn1 = b_hh1[gn];

    // per-thread weight bases (quad layout: (kk*G_+g)*4), loop stride G_*4
    const float* wih0_r = Wq_ih0 + gr * 4;
    const float* wih0_z = Wq_ih0 + gz * 4;
    const float* wih0_n = Wq_ih0 + gn * 4;
    const float* whh0_r = Wq_hh0 + gr * 4;
    const float* whh0_z = Wq_hh0 + gz * 4;
    const float* whh0_n = Wq_hh0 + gn * 4;
    const float* wih1_r = Wq_ih1 + gr * 4;
    const float* wih1_z = Wq_ih1 + gz * 4;
    const float* wih1_n = Wq_ih1 + gn * 4;
    const float* wh1_r  = Wh1 + gr * 4;
    const float* wh1_z  = Wh1 + gz * 4;
    const float* wh1_n  = Wh1 + gn * 4;

    float h0r[ROWS], h1r[ROWS];           // own hidden unit, register-resident
#pragma unroll
    for (int r = 0; r < ROWS; r++) { h0r[r] = 0.f; h1r[r] = 0.f; }

    __syncthreads();

    for (int t = 0; t < T_; ++t) {
        // stage x[:, t, :]  (8 rows x 32 floats, 2 per thread, coalesced)
#pragma unroll
        for (int it = 0; it < (ROWS * F_) / NTHR; ++it) {
            int idx = j + it * NTHR;
            int r = idx >> 5, c = idx & 31;
            xes[r * KX_ + c] = x[((size_t)(b0 + r) * T_ + t) * F_ + c];
        }
        __syncthreads();

        // ============== layer 0 ==============
        u64 ar[ROWS], az[ROWS], axn[ROWS], ahn[ROWS];
#pragma unroll
        for (int r = 0; r < ROWS; r++) { ar[r] = 0; az[r] = 0; axn[r] = 0; ahn[r] = 0; }

        // ih part: xcat(48) — W_ih0 stays L1-resident (.ca)
#pragma unroll 4
        for (int kk = 0; kk < KX_ / 4; ++kk) {
            ulonglong2 wr = *(const ulonglong2*)(wih0_r + kk * G_ * 4);
            ulonglong2 wz = *(const ulonglong2*)(wih0_z + kk * G_ * 4);
            ulonglong2 wn = *(const ulonglong2*)(wih0_n + kk * G_ * 4);
#pragma unroll
            for (int r = 0; r < ROWS; r++) {
                ulonglong2 v = *(const ulonglong2*)(xes + r * KX_ + kk * 4);
                ar[r]  = fma2(wr.x, v.x, ar[r]);  ar[r]  = fma2(wr.y, v.y, ar[r]);
                az[r]  = fma2(wz.x, v.x, az[r]);  az[r]  = fma2(wz.y, v.y, az[r]);
                axn[r] = fma2(wn.x, v.x, axn[r]); axn[r] = fma2(wn.y, v.y, axn[r]);
            }
        }
        // hh part: h0(128) — streamed via .cg
#pragma unroll 4
        for (int kk = 0; kk < H_ / 4; ++kk) {
            ulonglong2 wr = ldcg128(whh0_r + kk * G_ * 4);
            ulonglong2 wz = ldcg128(whh0_z + kk * G_ * 4);
            ulonglong2 wn = ldcg128(whh0_n + kk * G_ * 4);
#pragma unroll
            for (int r = 0; r < ROWS; r++) {
                ulonglong2 v = *(const ulonglong2*)(h0s + r * H_ + kk * 4);
                ar[r]  = fma2(wr.x, v.x, ar[r]);  ar[r]  = fma2(wr.y, v.y, ar[r]);
                az[r]  = fma2(wz.x, v.x, az[r]);  az[r]  = fma2(wz.y, v.y, az[r]);
                ahn[r] = fma2(wn.x, v.x, ahn[r]); ahn[r] = fma2(wn.y, v.y, ahn[r]);
            }
        }
        // gate nonlinearity + h0 update, fully register-local
#pragma unroll
        for (int r = 0; r < ROWS; r++) {
            float rr = sigmoidf_(hsum2(ar[r]) + br0);
            float zz = sigmoidf_(hsum2(az[r]) + bz0);
            float nn = tanhf_(hsum2(axn[r]) + bxn0 + rr * (hsum2(ahn[r]) + bhn0));
            float hn = nn + zz * (h0r[r] - nn);
            h0r[r] = hn;
            h0s[r * H_ + j] = hn;
        }
        __syncthreads();

        // ============== layer 1 ==============
#pragma unroll
        for (int r = 0; r < ROWS; r++) { ar[r] = 0; az[r] = 0; axn[r] = 0; ahn[r] = 0; }
#pragma unroll 2
        for (int kk = 0; kk < H_ / 4; ++kk) {
            ulonglong2 uw_r = ldcg128(wih1_r + kk * G_ * 4);   // stream .cg
            ulonglong2 uw_z = ldcg128(wih1_z + kk * G_ * 4);
            ulonglong2 uw_n = ldcg128(wih1_n + kk * G_ * 4);
            ulonglong2 vw_r = *(const ulonglong2*)(wh1_r + kk * G_ * 4);  // SMEM
            ulonglong2 vw_z = *(const ulonglong2*)(wh1_z + kk * G_ * 4);
            ulonglong2 vw_n = *(const ulonglong2*)(wh1_n + kk * G_ * 4);
#pragma unroll
            for (int r = 0; r < ROWS; r++) {
                ulonglong2 u = *(const ulonglong2*)(h0s + r * H_ + kk * 4);
                ulonglong2 v = *(const ulonglong2*)(h1s + r * H_ + kk * 4);
                ar[r]  = fma2(uw_r.x, u.x, ar[r]);  ar[r]  = fma2(uw_r.y, u.y, ar[r]);
                az[r]  = fma2(uw_z.x, u.x, az[r]);  az[r]  = fma2(uw_z.y, u.y, az[r]);
                axn[r] = fma2(uw_n.x, u.x, axn[r]); axn[r] = fma2(uw_n.y, u.y, axn[r]);
                ar[r]  = fma2(vw_r.x, v.x, ar[r]);  ar[r]  = fma2(vw_r.y, v.y, ar[r]);
                az[r]  = fma2(vw_z.x, v.x, az[r]);  az[r]  = fma2(vw_z.y, v.y, az[r]);
                ahn[r] = fma2(vw_n.x, v.x, ahn[r]); ahn[r] = fma2(vw_n.y, v.y, ahn[r]);
            }
        }
#pragma unroll
        for (int r = 0; r < ROWS; r++) {
            float rr = sigmoidf_(hsum2(ar[r]) + br1);
            float zz = sigmoidf_(hsum2(az[r]) + bz1);
            float nn = tanhf_(hsum2(axn[r]) + bxn1 + rr * (hsum2(ahn[r]) + bhn1));
            float hn = nn + zz * (h1r[r] - nn);
            h1r[r] = hn;
            h1s[r * H_ + j] = hn;
        }
        __syncthreads();
    }

    // ============== head ==============
    // hid = relu(h1 @ head_w1^T + b1); y = hid @ head_w2^T + b2
    {
        const float w2 = head_w2[j];
        const float b1v = head_b1[j];
        float acc[ROWS];
#pragma unroll
        for (int r = 0; r < ROWS; r++) acc[r] = b1v;
        for (int k = 0; k < H_; k += 4) {
            float4 w = *(const float4*)(head_w1 + (size_t)j * H_ + k);
#pragma unroll
            for (int r = 0; r < ROWS; r++) {
                float4 v = *(const float4*)(h1s + r * H_ + k);
                acc[r] += w.x * v.x + w.y * v.y + w.z * v.z + w.w * v.w;
            }
        }
#pragma unroll
        for (int r = 0; r < ROWS; r++) h0s[r * H_ + j] = fmaxf(acc[r], 0.f) * w2;
    }
    __syncthreads();
    if (j < ROWS) {
        float acc = head_b2[0];
        for (int k = 0; k < H_; k++) acc += h0s[j * H_ + k];
        y[b0 + j] = acc;
    }
}

extern "C" void kernel_launch(void* const* d_in, const int* in_sizes, int n_in,
                              void* d_out, int out_size) {
    const float* x       = (const float*)d_in[0];
    const int*   ticker  = (const int*)  d_in[1];
    const float* embed   = (const float*)d_in[2];
    const float* W_ih0   = (const float*)d_in[3];
    const float* W_hh0   = (const float*)d_in[4];
    const float* b_ih0   = (const float*)d_in[5];
    const float* b_hh0   = (const float*)d_in[6];
    const float* W_ih1   = (const float*)d_in[7];
    const float* W_hh1   = (const float*)d_in[8];
    const float* b_ih1   = (const float*)d_in[9];
    const float* b_hh1   = (const float*)d_in[10];
    const float* head_w1 = (const float*)d_in[11];
    const float* head_b1 = (const float*)d_in[12];
    const float* head_w2 = (const float*)d_in[13];
    const float* head_b2 = (const float*)d_in[14];

    const int smem_bytes = (H_ * G_ + 2 * ROWS * H_ + ROWS * KX_) * sizeof(float);
    cudaFuncSetAttribute(gru_kernel, cudaFuncAttributeMaxDynamicSharedMemorySize,
                         smem_bytes);

    prep_kernel<<<(H_ * G_ + 255) / 256, 256>>>(W_ih0, W_hh0, W_ih1, W_hh1);
    gru_kernel<<<NBLK, NTHR, smem_bytes>>>(x, ticker, embed,
                                           b_ih0, b_hh0, b_ih1, b_hh1,
                                           head_w1, head_b1, head_w2, head_b2,
                                           (float*)d_out);
}

// round 3
// speedup vs baseline: 1.1410x; 1.0330x over previous
#include <cuda_runtime.h>

#define B_   1024
#define T_   512
#define F_   32
#define E_   16
#define H_   128
#define G_   384      // 3*H
#define KX_  48       // F + E
#define ROWS 8        // batch rows per block
#define NBLK (B_/ROWS)  // 128 blocks
#define NTHR 512      // 4 groups of 128: (row-half, k-half)
#define RP   4        // rows per row-group

typedef unsigned long long u64;

// Quad-packed transposed weights: layout [k/4][g][4]
__device__ __align__(16) float Wq_ih0[KX_*G_];
__device__ __align__(16) float Wq_hh0[H_*G_];
__device__ __align__(16) float Wq_ih1[H_*G_];
__device__ __align__(16) float Wq_hh1[H_*G_];

__global__ void prep_kernel(const float* __restrict__ W_ih0,
                            const float* __restrict__ W_hh0,
                            const float* __restrict__ W_ih1,
                            const float* __restrict__ W_hh1) {
    int idx = blockIdx.x * blockDim.x + threadIdx.x;
    if (idx < KX_ * G_) {
        int g = idx / KX_, k = idx % KX_;
        Wq_ih0[((k >> 2) * G_ + g) * 4 + (k & 3)] = W_ih0[idx];
    }
    if (idx < H_ * G_) {
        int g = idx / H_, k = idx % H_;
        int dst = ((k >> 2) * G_ + g) * 4 + (k & 3);
        Wq_hh0[dst] = W_hh0[idx];
        Wq_ih1[dst] = W_ih1[idx];
        Wq_hh1[dst] = W_hh1[idx];
    }
}

__device__ __forceinline__ u64 fma2(u64 a, u64 b, u64 c) {
    u64 d;
    asm("fma.rn.f32x2 %0, %1, %2, %3;" : "=l"(d) : "l"(a), "l"(b), "l"(c));
    return d;
}
__device__ __forceinline__ float hsum2(u64 a) {
    float l, h;
    asm("mov.b64 {%0, %1}, %2;" : "=f"(l), "=f"(h) : "l"(a));
    return l + h;
}
__device__ __forceinline__ ulonglong2 ldcg128(const float* p) {
    ulonglong2 v;
    asm("ld.global.cg.v2.u64 {%0, %1}, [%2];" : "=l"(v.x), "=l"(v.y) : "l"(p));
    return v;
}
__device__ __forceinline__ float sigmoidf_(float v) {
    return 1.f / (1.f + __expf(-v));
}
__device__ __forceinline__ float tanhf_(float v) {
    v = fminf(fmaxf(v, -15.f), 15.f);
    float e = __expf(2.f * v);
    return (e - 1.f) / (e + 1.f);
}

__global__ void __launch_bounds__(NTHR, 1) gru_kernel(
    const float* __restrict__ x,         // (B, T, F)
    const int*   __restrict__ ticker,    // (B,)
    const float* __restrict__ embed,     // (N_TICKERS, E)
    const float* __restrict__ b_ih0, const float* __restrict__ b_hh0,
    const float* __restrict__ b_ih1, const float* __restrict__ b_hh1,
    const float* __restrict__ head_w1, const float* __restrict__ head_b1,
    const float* __restrict__ head_w2, const float* __restrict__ head_b2,
    float* __restrict__ y)               // (B,)
{
    extern __shared__ float sm[];
    float* Wh1  = sm;                       // 192KB: W_hh1 parked
    float* h0s  = sm + H_ * G_;             // ROWS*H_
    float* h1s  = h0s + ROWS * H_;          // ROWS*H_
    float* xes  = h1s + ROWS * H_;          // ROWS*KX_
    float* exch = xes + ROWS * KX_;         // NTHR*8 floats (16KB)

    const int tid = threadIdx.x;
    const int j   = tid & 127;              // hidden unit
    const int kg  = (tid >> 7) & 1;         // k-half
    const int rg  = tid >> 8;               // row-half
    const int rbase = rg * RP;
    const int b0  = blockIdx.x * ROWS;

    // park W_hh1 in SMEM
    {
        const float4* src = (const float4*)Wq_hh1;
        float4* dst = (float4*)Wh1;
        for (int i = tid; i < H_ * G_ / 4; i += NTHR) dst[i] = src[i];
    }
    for (int i = tid; i < ROWS * H_; i += NTHR) { h0s[i] = 0.f; h1s[i] = 0.f; }
    if (tid < ROWS * E_) {
        int r = tid / E_, e = tid % E_;
        xes[r * KX_ + F_ + e] = embed[(size_t)ticker[b0 + r] * E_ + e];
    }

    const int gr = j, gz = H_ + j, gn = 2 * H_ + j;
    const float br0  = b_ih0[gr] + b_hh0[gr];
    const float bz0  = b_ih0[gz] + b_hh0[gz];
    const float bxn0 = b_ih0[gn], bhn0 = b_hh0[gn];
    const float br1  = b_ih1[gr] + b_hh1[gr];
    const float bz1  = b_ih1[gz] + b_hh1[gz];
    const float bxn1 = b_ih1[gn], bhn1 = b_hh1[gn];

    // k ranges for this k-group
    const int kx0 = kg * (KX_ / 8);         // ih0 quads: [kg*6, kg*6+6)
    const int kh0 = kg * (H_ / 8);          // h quads:   [kg*16, kg*16+16)

    // weight bases (quad layout: (kk*G_+g)*4)
    const float* wih0_r = Wq_ih0 + gr * 4 + kx0 * G_ * 4;
    const float* wih0_z = Wq_ih0 + gz * 4 + kx0 * G_ * 4;
    const float* wih0_n = Wq_ih0 + gn * 4 + kx0 * G_ * 4;
    const float* whh0_r = Wq_hh0 + gr * 4 + kh0 * G_ * 4;
    const float* whh0_z = Wq_hh0 + gz * 4 + kh0 * G_ * 4;
    const float* whh0_n = Wq_hh0 + gn * 4 + kh0 * G_ * 4;
    const float* wih1_r = Wq_ih1 + gr * 4 + kh0 * G_ * 4;
    const float* wih1_z = Wq_ih1 + gz * 4 + kh0 * G_ * 4;
    const float* wih1_n = Wq_ih1 + gn * 4 + kh0 * G_ * 4;
    const float* wh1_r  = Wh1 + gr * 4 + kh0 * G_ * 4;
    const float* wh1_z  = Wh1 + gz * 4 + kh0 * G_ * 4;
    const float* wh1_n  = Wh1 + gn * 4 + kh0 * G_ * 4;

    const int lo = (kg ^ 1) * 2;            // local rows I export
    const int lf = kg * 2;                  // local rows I finalize
    float* my_exch = exch + tid * 8;
    const float* pa_exch = exch + (tid ^ 128) * 8;

    __syncthreads();

    for (int t = 0; t < T_; ++t) {
        // stage x[:, t, :] (8 rows x 32 floats)
        if (tid < ROWS * F_) {
            int r = tid >> 5, c = tid & 31;
            xes[r * KX_ + c] = x[((size_t)(b0 + r) * T_ + t) * F_ + c];
        }
        __syncthreads();

        // ============== layer 0 ==============
        u64 ar[RP], az[RP], axn[RP], ahn[RP];
#pragma unroll
        for (int r = 0; r < RP; r++) { ar[r] = 0; az[r] = 0; axn[r] = 0; ahn[r] = 0; }

#pragma unroll 2
        for (int kk = 0; kk < KX_ / 8; ++kk) {
            ulonglong2 wr = ldcg128(wih0_r + kk * G_ * 4);
            ulonglong2 wz = ldcg128(wih0_z + kk * G_ * 4);
            ulonglong2 wn = ldcg128(wih0_n + kk * G_ * 4);
#pragma unroll
            for (int r = 0; r < RP; r++) {
                ulonglong2 v = *(const ulonglong2*)(xes + (rbase + r) * KX_ + (kx0 + kk) * 4);
                ar[r]  = fma2(wr.x, v.x, ar[r]);  ar[r]  = fma2(wr.y, v.y, ar[r]);
                az[r]  = fma2(wz.x, v.x, az[r]);  az[r]  = fma2(wz.y, v.y, az[r]);
                axn[r] = fma2(wn.x, v.x, axn[r]); axn[r] = fma2(wn.y, v.y, axn[r]);
            }
        }
#pragma unroll 2
        for (int kk = 0; kk < H_ / 8; ++kk) {
            ulonglong2 wr = ldcg128(whh0_r + kk * G_ * 4);
            ulonglong2 wz = ldcg128(whh0_z + kk * G_ * 4);
            ulonglong2 wn = ldcg128(whh0_n + kk * G_ * 4);
#pragma unroll
            for (int r = 0; r < RP; r++) {
                ulonglong2 v = *(const ulonglong2*)(h0s + (rbase + r) * H_ + (kh0 + kk) * 4);
                ar[r]  = fma2(wr.x, v.x, ar[r]);  ar[r]  = fma2(wr.y, v.y, ar[r]);
                az[r]  = fma2(wz.x, v.x, az[r]);  az[r]  = fma2(wz.y, v.y, az[r]);
                ahn[r] = fma2(wn.x, v.x, ahn[r]); ahn[r] = fma2(wn.y, v.y, ahn[r]);
            }
        }
        {
            // export partials for the 2 rows my k-partner finalizes
            float4 e0 = make_float4(hsum2(ar[lo]), hsum2(az[lo]), hsum2(axn[lo]), hsum2(ahn[lo]));
            float4 e1 = make_float4(hsum2(ar[lo+1]), hsum2(az[lo+1]), hsum2(axn[lo+1]), hsum2(ahn[lo+1]));
            *(float4*)(my_exch)     = e0;
            *(float4*)(my_exch + 4) = e1;
            __syncthreads();
#pragma unroll
            for (int i = 0; i < 2; ++i) {
                int lr = lf + i, r = rbase + lr;
                float4 q = *(const float4*)(pa_exch + i * 4);
                float R  = sigmoidf_(hsum2(ar[lr])  + q.x + br0);
                float Z  = sigmoidf_(hsum2(az[lr])  + q.y + bz0);
                float NN = tanhf_(hsum2(axn[lr]) + q.z + bxn0 +
                                  R * (hsum2(ahn[lr]) + q.w + bhn0));
                float ho = h0s[r * H_ + j];
                h0s[r * H_ + j] = NN + Z * (ho - NN);
            }
            __syncthreads();
        }

        // ============== layer 1 ==============
#pragma unroll
        for (int r = 0; r < RP; r++) { ar[r] = 0; az[r] = 0; axn[r] = 0; ahn[r] = 0; }
#pragma unroll 2
        for (int kk = 0; kk < H_ / 8; ++kk) {
            ulonglong2 uw_r = ldcg128(wih1_r + kk * G_ * 4);
            ulonglong2 uw_z = ldcg128(wih1_z + kk * G_ * 4);
            ulonglong2 uw_n = ldcg128(wih1_n + kk * G_ * 4);
            ulonglong2 vw_r = *(const ulonglong2*)(wh1_r + kk * G_ * 4);
            ulonglong2 vw_z = *(const ulonglong2*)(wh1_z + kk * G_ * 4);
            ulonglong2 vw_n = *(const ulonglong2*)(wh1_n + kk * G_ * 4);
#pragma unroll
            for (int r = 0; r < RP; r++) {
                ulonglong2 u = *(const ulonglong2*)(h0s + (rbase + r) * H_ + (kh0 + kk) * 4);
                ulonglong2 v = *(const ulonglong2*)(h1s + (rbase + r) * H_ + (kh0 + kk) * 4);
                ar[r]  = fma2(uw_r.x, u.x, ar[r]);  ar[r]  = fma2(uw_r.y, u.y, ar[r]);
                az[r]  = fma2(uw_z.x, u.x, az[r]);  az[r]  = fma2(uw_z.y, u.y, az[r]);
                axn[r] = fma2(uw_n.x, u.x, axn[r]); axn[r] = fma2(uw_n.y, u.y, axn[r]);
                ar[r]  = fma2(vw_r.x, v.x, ar[r]);  ar[r]  = fma2(vw_r.y, v.y, ar[r]);
                az[r]  = fma2(vw_z.x, v.x, az[r]);  az[r]  = fma2(vw_z.y, v.y, az[r]);
                ahn[r] = fma2(vw_n.x, v.x, ahn[r]); ahn[r] = fma2(vw_n.y, v.y, ahn[r]);
            }
        }
        {
            float4 e0 = make_float4(hsum2(ar[lo]), hsum2(az[lo]), hsum2(axn[lo]), hsum2(ahn[lo]));
            float4 e1 = make_float4(hsum2(ar[lo+1]), hsum2(az[lo+1]), hsum2(axn[lo+1]), hsum2(ahn[lo+1]));
            *(float4*)(my_exch)     = e0;
            *(float4*)(my_exch + 4) = e1;
            __syncthreads();
#pragma unroll
            for (int i = 0; i < 2; ++i) {
                int lr = lf + i, r = rbase + lr;
                float4 q = *(const float4*)(pa_exch + i * 4);
                float R  = sigmoidf_(hsum2(ar[lr])  + q.x + br1);
                float Z  = sigmoidf_(hsum2(az[lr])  + q.y + bz1);
                float NN = tanhf_(hsum2(axn[lr]) + q.z + bxn1 +
                                  R * (hsum2(ahn[lr]) + q.w + bhn1));
                float ho = h1s[r * H_ + j];
                h1s[r * H_ + j] = NN + Z * (ho - NN);
            }
            __syncthreads();
        }
    }

    // ============== head ==============
    if (tid < H_) {
        const float w2  = head_w2[tid];
        const float b1v = head_b1[tid];
        float acc[ROWS];
#pragma unroll
        for (int r = 0; r < ROWS; r++) acc[r] = b1v;
        for (int k = 0; k < H_; k += 4) {
            float4 w = *(const float4*)(head_w1 + (size_t)tid * H_ + k);
#pragma unroll
            for (int r = 0; r < ROWS; r++) {
                float4 v = *(const float4*)(h1s + r * H_ + k);
                acc[r] += w.x * v.x + w.y * v.y + w.z * v.z + w.w * v.w;
            }
        }
#pragma unroll
        for (int r = 0; r < ROWS; r++) exch[r * H_ + tid] = fmaxf(acc[r], 0.f) * w2;
    }
    __syncthreads();
    if (tid < ROWS) {
        float acc = head_b2[0];
        for (int k = 0; k < H_; k++) acc += exch[tid * H_ + k];
        y[b0 + tid] = acc;
    }
}

extern "C" void kernel_launch(void* const* d_in, const int* in_sizes, int n_in,
                              void* d_out, int out_size) {
    const float* x       = (const float*)d_in[0];
    const int*   ticker  = (const int*)  d_in[1];
    const float* embed   = (const float*)d_in[2];
    const float* W_ih0   = (const float*)d_in[3];
    const float* W_hh0   = (const float*)d_in[4];
    const float* b_ih0   = (const float*)d_in[5];
    const float* b_hh0   = (const float*)d_in[6];
    const float* W_ih1   = (const float*)d_in[7];
    const float* W_hh1   = (const float*)d_in[8];
    const float* b_ih1   = (const float*)d_in[9];
    const float* b_hh1   = (const float*)d_in[10];
    const float* head_w1 = (const float*)d_in[11];
    const float* head_b1 = (const float*)d_in[12];
    const float* head_w2 = (const float*)d_in[13];
    const float* head_b2 = (const float*)d_in[14];

    const int smem_bytes = (H_ * G_ + 2 * ROWS * H_ + ROWS * KX_ + NTHR * 8)
                           * sizeof(float);
    cudaFuncSetAttribute(gru_kernel, cudaFuncAttributeMaxDynamicSharedMemorySize,
                         smem_bytes);

    prep_kernel<<<(H_ * G_ + 255) / 256, 256>>>(W_ih0, W_hh0, W_ih1, W_hh1);
    gru_kernel<<<NBLK, NTHR, smem_bytes>>>(x, ticker, embed,
                                           b_ih0, b_hh0, b_ih1, b_hh1,
                                           head_w1, head_b1, head_w2, head_b2,
                                           (float*)d_out);
}